// round 16
// baseline (speedup 1.0000x reference)
#include <cuda_runtime.h>
#include <cuda_bf16.h>

// ---------------------------------------------------------------------------
// Problem constants (edge_index / batch_vec are int32 — JAX x64 disabled)
// NOTE: tcgen05 is unavailable — harness builds via compute_103 (no 'a'),
// which rejects all tcgen05/TMEM PTX. mma.sync is the tensor path here.
// ---------------------------------------------------------------------------
#define N_NODES   50000
#define N_EDGES   800000
#define IN_C      128
#define HID_C     256
#define OUT_C     128
#define NUM_GRAPHS 128
#define EPS_BN    1e-5f

// ---------------------------------------------------------------------------
// Scratch (device globals). Ping-pong feature buffers:
//   L1: agg(x)->buf0 ; gemm buf0->buf1
//   L2: gemm(BN1) buf1->buf0 ; agg buf0->buf1
//   L3: gemm(BN2) buf1->buf0 ; agg buf0->buf1 ; pool(BN3) reads buf1
// ---------------------------------------------------------------------------
__device__ float g_buf0[N_NODES * HID_C];
__device__ float g_buf1[N_NODES * HID_C];
__device__ __nv_bfloat16 g_whi[HID_C * HID_C];   // W hi plane, [K][N] row-major
__device__ __nv_bfloat16 g_wlo[HID_C * HID_C];   // W lo plane
__device__ float g_deg [N_NODES];
__device__ float g_dinv[N_NODES];
__device__ int   g_rowptr[N_NODES + 1];
__device__ int   g_cursor[N_NODES];
__device__ int   g_col[N_EDGES];
__device__ float g_val[N_EDGES];
__device__ int   g_lex [N_NODES];
__device__ int   g_boff[256];
__device__ float g_sums  [3 * HID_C];
__device__ float g_sumsqs[3 * HID_C];
__device__ float g_scale[HID_C];
__device__ float g_shift[HID_C];
__device__ float g_cnt  [NUM_GRAPHS];
__device__ float g_pool [NUM_GRAPHS * OUT_C];

// ---------------------------------------------------------------------------
// MMA / ldmatrix wrappers
// ---------------------------------------------------------------------------
__device__ __forceinline__ unsigned smem_u32(const void* p) {
    return (unsigned)__cvta_generic_to_shared(p);
}
__device__ __forceinline__ void ldsm4(unsigned& r0, unsigned& r1,
                                      unsigned& r2, unsigned& r3, unsigned a) {
    asm volatile("ldmatrix.sync.aligned.m8n8.x4.shared.b16 {%0,%1,%2,%3}, [%4];"
                 : "=r"(r0), "=r"(r1), "=r"(r2), "=r"(r3) : "r"(a));
}
__device__ __forceinline__ void ldsm2t(unsigned& r0, unsigned& r1, unsigned a) {
    asm volatile("ldmatrix.sync.aligned.m8n8.x2.trans.shared.b16 {%0,%1}, [%2];"
                 : "=r"(r0), "=r"(r1) : "r"(a));
}
__device__ __forceinline__ void mma16816(float* c, const unsigned* a, const unsigned* b) {
    asm volatile("mma.sync.aligned.m16n8k16.row.col.f32.bf16.bf16.f32 "
                 "{%0,%1,%2,%3}, {%4,%5,%6,%7}, {%8,%9}, {%0,%1,%2,%3};"
                 : "+f"(c[0]), "+f"(c[1]), "+f"(c[2]), "+f"(c[3])
                 : "r"(a[0]), "r"(a[1]), "r"(a[2]), "r"(a[3]), "r"(b[0]), "r"(b[1]));
}

// ---------------------------------------------------------------------------
// Weight hi/lo bf16 split (layout preserved: [K][N] row-major)
// ---------------------------------------------------------------------------
__global__ void k_split_w(const float* __restrict__ src, int n) {
    int i = blockIdx.x * blockDim.x + threadIdx.x;
    if (i < n) {
        float v = src[i];
        __nv_bfloat16 h = __float2bfloat16(v);
        g_whi[i] = h;
        g_wlo[i] = __float2bfloat16(v - __bfloat162float(h));
    }
}

// ---------------------------------------------------------------------------
// Combined init
// ---------------------------------------------------------------------------
__global__ void k_init() {
    int i = blockIdx.x * blockDim.x + threadIdx.x;
    if (i < N_NODES) g_deg[i] = 1.0f;
    if (i < 3 * HID_C) { g_sums[i] = 0.0f; g_sumsqs[i] = 0.0f; }
    if (i < NUM_GRAPHS * OUT_C) g_pool[i] = 0.0f;
    if (i < NUM_GRAPHS) g_cnt[i] = 0.0f;
}

__global__ void k_deg_edges(const int* __restrict__ ei) {
    int e = blockIdx.x * blockDim.x + threadIdx.x;
    if (e < N_EDGES) atomicAdd(&g_deg[ei[N_EDGES + e]], 1.0f);
}

__global__ void k_dinv() {
    int i = blockIdx.x * blockDim.x + threadIdx.x;
    if (i < N_NODES) {
        float d = g_deg[i];
        g_dinv[i] = (d > 0.0f) ? rsqrtf(d) : 0.0f;
    }
}

// ---------------------------------------------------------------------------
// Two-level parallel exclusive scan of (deg-1) -> rowptr / cursor
// ---------------------------------------------------------------------------
#define SCAN_NB ((N_NODES + 255) / 256)

__global__ void k_scan_local() {
    __shared__ int s[256];
    int t = threadIdx.x, b = blockIdx.x;
    int i = b * 256 + t;
    int v = (i < N_NODES) ? ((int)g_deg[i] - 1) : 0;
    s[t] = v;
    __syncthreads();
    #pragma unroll
    for (int off = 1; off < 256; off <<= 1) {
        int u = (t >= off) ? s[t - off] : 0;
        __syncthreads();
        s[t] += u;
        __syncthreads();
    }
    if (i < N_NODES) g_lex[i] = s[t] - v;
    if (t == 255) g_boff[b] = s[255];
}

__global__ void k_scan_bsum() {
    __shared__ int s[256];
    int t = threadIdx.x;
    int v = (t < SCAN_NB) ? g_boff[t] : 0;
    s[t] = v;
    __syncthreads();
    #pragma unroll
    for (int off = 1; off < 256; off <<= 1) {
        int u = (t >= off) ? s[t - off] : 0;
        __syncthreads();
        s[t] += u;
        __syncthreads();
    }
    if (t < SCAN_NB) g_boff[t] = s[t] - v;
    if (t == 255) g_rowptr[N_NODES] = s[255];
}

__global__ void k_scan_final() {
    int i = blockIdx.x * blockDim.x + threadIdx.x;
    if (i < N_NODES) {
        int r = g_lex[i] + g_boff[i >> 8];
        g_rowptr[i] = r;
        g_cursor[i] = r;
    }
}

__global__ void k_fill(const int* __restrict__ ei) {
    int e = blockIdx.x * blockDim.x + threadIdx.x;
    if (e < N_EDGES) {
        int s = ei[e];
        int d = ei[N_EDGES + e];
        int pos = atomicAdd(&g_cursor[d], 1);
        g_col[pos] = s;
        g_val[pos] = g_dinv[s] * g_dinv[d];
    }
}

// ---------------------------------------------------------------------------
// CSR aggregation
// ---------------------------------------------------------------------------
template <int C, bool EXT>
__global__ void k_aggregate(const float* __restrict__ xin) {
    const float* src = EXT ? xin : (const float*)g_buf0;
    float*       dst = EXT ? (float*)g_buf0 : (float*)g_buf1;
    int i = blockIdx.x;
    int c = threadIdx.x;
    size_t base = (size_t)i * C + c;
    float w = g_dinv[i];
    float acc0 = w * w * src[base];
    float acc1 = 0.f, acc2 = 0.f, acc3 = 0.f;
    int e  = g_rowptr[i];
    int e1 = g_rowptr[i + 1];
    for (; e + 4 <= e1; e += 4) {
        int   s0 = g_col[e],     s1 = g_col[e + 1];
        int   s2 = g_col[e + 2], s3 = g_col[e + 3];
        float v0 = g_val[e],     v1 = g_val[e + 1];
        float v2 = g_val[e + 2], v3 = g_val[e + 3];
        acc0 += v0 * src[(size_t)s0 * C + c];
        acc1 += v1 * src[(size_t)s1 * C + c];
        acc2 += v2 * src[(size_t)s2 * C + c];
        acc3 += v3 * src[(size_t)s3 * C + c];
    }
    for (; e < e1; e++)
        acc0 += g_val[e] * src[(size_t)g_col[e] * C + c];
    dst[base] = (acc0 + acc1) + (acc2 + acc3);
}

// ---------------------------------------------------------------------------
// Tensor-core GEMM, bf16 hi/lo compensated, fused BN+ReLU on A.
// 512 threads = 16 warps (4m x 4n), warp tile 32x32, block tile 128x128, BK=32.
// Halved per-warp acc (acc[2][4][4]=32 regs) -> ~90 regs/thread; one CTA/SM
// but 4 warps/SMSP (vs 2 at 256 threads) for latency hiding. No reg cap —
// the 128-reg cap caused mainloop spills (R12).
// BN=false: g_buf0 -> g_buf1 ; BN=true: relu(BN(g_buf1)) -> g_buf0
// ---------------------------------------------------------------------------
#define GA_STR 40     // A smem row stride (bf16 elems)
#define GB_STR 136    // B smem row stride

template <bool BN>
__global__ __launch_bounds__(512)
void k_gemm_tc(int M, int N, int K) {
    const float* A = BN ? (const float*)g_buf1 : (const float*)g_buf0;
    float*       D = BN ? (float*)g_buf0 : (float*)g_buf1;
    __shared__ __nv_bfloat16 sa[2][128 * GA_STR];
    __shared__ __nv_bfloat16 sb[2][32 * GB_STR];
    __shared__ float sscale[HID_C], sshift[HID_C];

    int tid = threadIdx.x, lane = tid & 31, warp = tid >> 5;
    int wm = warp >> 2, wn = warp & 3;            // 4 x 4 warp grid
    int bm = blockIdx.y * 128, bn = blockIdx.x * 128;

    if (BN) {
        for (int i = tid; i < K; i += 512) {
            sscale[i] = g_scale[i];
            sshift[i] = g_shift[i];
        }
    }
    __syncthreads();

    float acc[2][4][4];
    #pragma unroll
    for (int i = 0; i < 2; i++)
        #pragma unroll
        for (int j = 0; j < 4; j++)
            #pragma unroll
            for (int q = 0; q < 4; q++) acc[i][j][q] = 0.0f;

    for (int k0 = 0; k0 < K; k0 += 32) {
        // --- A: 128m x 32k fp32 (1024 float4; 2/thread), BN+ReLU, hi/lo ---
        #pragma unroll
        for (int r = 0; r < 2; r++) {
            int f = tid + 512 * r;
            int m = f >> 3, kc = f & 7;
            float4 v = make_float4(0.f, 0.f, 0.f, 0.f);
            if (bm + m < M)
                v = *(const float4*)&A[(size_t)(bm + m) * K + k0 + kc * 4];
            if (BN) {
                int kb = k0 + kc * 4;
                v.x = fmaxf(v.x * sscale[kb + 0] + sshift[kb + 0], 0.f);
                v.y = fmaxf(v.y * sscale[kb + 1] + sshift[kb + 1], 0.f);
                v.z = fmaxf(v.z * sscale[kb + 2] + sshift[kb + 2], 0.f);
                v.w = fmaxf(v.w * sscale[kb + 3] + sshift[kb + 3], 0.f);
            }
            __nv_bfloat16 hx = __float2bfloat16(v.x), hy = __float2bfloat16(v.y);
            __nv_bfloat16 hz = __float2bfloat16(v.z), hw = __float2bfloat16(v.w);
            union { __nv_bfloat162 b[2]; uint2 u; } Hi, Lo;
            Hi.b[0] = __nv_bfloat162(hx, hy);
            Hi.b[1] = __nv_bfloat162(hz, hw);
            Lo.b[0] = __nv_bfloat162(__float2bfloat16(v.x - __bfloat162float(hx)),
                                     __float2bfloat16(v.y - __bfloat162float(hy)));
            Lo.b[1] = __nv_bfloat162(__float2bfloat16(v.z - __bfloat162float(hz)),
                                     __float2bfloat16(v.w - __bfloat162float(hw)));
            *(uint2*)&sa[0][m * GA_STR + kc * 4] = Hi.u;
            *(uint2*)&sa[1][m * GA_STR + kc * 4] = Lo.u;
        }
        // --- B: 32k x 128n (512 uint4 per plane; 1/thread each) ---
        {
            int k = tid >> 4, nc = tid & 15;
            size_t off = (size_t)(k0 + k) * N + bn + nc * 8;
            *(uint4*)&sb[0][k * GB_STR + nc * 8] = *(const uint4*)&g_whi[off];
            *(uint4*)&sb[1][k * GB_STR + nc * 8] = *(const uint4*)&g_wlo[off];
        }
        __syncthreads();

        #pragma unroll
        for (int ks = 0; ks < 2; ks++) {
            int kk = ks * 16;
            unsigned ah[2][4], al[2][4], bh[4][2], bl[4][2];

            int tsel = lane >> 3, rowin = lane & 7;
            int arow_off = rowin + (tsel & 1) * 8;
            int akcol = kk + (tsel >> 1) * 8;
            #pragma unroll
            for (int mf = 0; mf < 2; mf++) {
                int row = wm * 32 + mf * 16 + arow_off;
                ldsm4(ah[mf][0], ah[mf][1], ah[mf][2], ah[mf][3],
                      smem_u32(&sa[0][row * GA_STR + akcol]));
                ldsm4(al[mf][0], al[mf][1], al[mf][2], al[mf][3],
                      smem_u32(&sa[1][row * GA_STR + akcol]));
            }
            int l16 = lane & 15;
            int bkrow = kk + (l16 >> 3) * 8 + (l16 & 7);
            #pragma unroll
            for (int nf = 0; nf < 4; nf++) {
                int n0 = wn * 32 + nf * 8;
                ldsm2t(bh[nf][0], bh[nf][1], smem_u32(&sb[0][bkrow * GB_STR + n0]));
                ldsm2t(bl[nf][0], bl[nf][1], smem_u32(&sb[1][bkrow * GB_STR + n0]));
            }

            #pragma unroll
            for (int mf = 0; mf < 2; mf++)
                #pragma unroll
                for (int nf = 0; nf < 4; nf++)
                    mma16816(acc[mf][nf], ah[mf], bh[nf]);
            #pragma unroll
            for (int mf = 0; mf < 2; mf++)
                #pragma unroll
                for (int nf = 0; nf < 4; nf++)
                    mma16816(acc[mf][nf], ah[mf], bl[nf]);
            #pragma unroll
            for (int mf = 0; mf < 2; mf++)
                #pragma unroll
                for (int nf = 0; nf < 4; nf++)
                    mma16816(acc[mf][nf], al[mf], bh[nf]);
        }
        __syncthreads();
    }

    int grp = lane >> 2, tg = lane & 3;
    #pragma unroll
    for (int mf = 0; mf < 2; mf++) {
        #pragma unroll
        for (int nf = 0; nf < 4; nf++) {
            int row = bm + wm * 32 + mf * 16 + grp;
            int col = bn + wn * 32 + nf * 8 + tg * 2;
            if (row < M)
                *(float2*)&D[(size_t)row * N + col] =
                    make_float2(acc[mf][nf][0], acc[mf][nf][1]);
            if (row + 8 < M)
                *(float2*)&D[(size_t)(row + 8) * N + col] =
                    make_float2(acc[mf][nf][2], acc[mf][nf][3]);
        }
    }
}

// ---------------------------------------------------------------------------
// BN statistics + finalize
// ---------------------------------------------------------------------------
template <int L, int C>
__global__ void k_bn_stats() {
    int c = threadIdx.x;
    float s = 0.0f, s2 = 0.0f;
    for (int i = blockIdx.x; i < N_NODES; i += gridDim.x) {
        float v = g_buf1[(size_t)i * C + c];
        s += v; s2 += v * v;
    }
    atomicAdd(&g_sums[L * HID_C + c], s);
    atomicAdd(&g_sumsqs[L * HID_C + c], s2);
}

template <int L, int C>
__global__ void k_bn_finalize(const float* __restrict__ gamma,
                              const float* __restrict__ beta) {
    int c = threadIdx.x;
    if (c < C) {
        float mu  = g_sums[L * HID_C + c] * (1.0f / N_NODES);
        float var = g_sumsqs[L * HID_C + c] * (1.0f / N_NODES) - mu * mu;
        float inv = rsqrtf(var + EPS_BN);
        float sc  = gamma[c] * inv;
        g_scale[c] = sc;
        g_shift[c] = beta[c] - mu * sc;
    }
}

// ---------------------------------------------------------------------------
// Global mean pool with layer-3 BN+ReLU fused on the read
// ---------------------------------------------------------------------------
__global__ void k_pool(const int* __restrict__ batch) {
    int c = threadIdx.x;
    int per = (N_NODES + gridDim.x - 1) / gridDim.x;
    int i0 = blockIdx.x * per;
    int i1 = min(i0 + per, N_NODES);
    if (i0 >= i1) return;

    float sc = g_scale[c], sh = g_shift[c];
    int curg = batch[i0];
    float acc = 0.0f, n = 0.0f;
    for (int i = i0; i < i1; i++) {
        int g = batch[i];
        if (g != curg) {
            atomicAdd(&g_pool[curg * OUT_C + c], acc);
            if (c == 0) atomicAdd(&g_cnt[curg], n);
            acc = 0.0f; n = 0.0f; curg = g;
        }
        acc += fmaxf(g_buf1[(size_t)i * OUT_C + c] * sc + sh, 0.0f);
        n += 1.0f;
    }
    atomicAdd(&g_pool[curg * OUT_C + c], acc);
    if (c == 0) atomicAdd(&g_cnt[curg], n);
}

__global__ void k_pool_div(float* __restrict__ out) {
    int i = blockIdx.x * blockDim.x + threadIdx.x;
    if (i < NUM_GRAPHS * OUT_C) {
        float cnt = g_cnt[i / OUT_C];
        out[i] = g_pool[i] / fmaxf(cnt, 1.0f);
    }
}

// ---------------------------------------------------------------------------
// Host orchestration (kernel launches ONLY — graph-capture safe)
// ---------------------------------------------------------------------------
extern "C" void kernel_launch(void* const* d_in, const int* in_sizes, int n_in,
                              void* d_out, int out_size) {
    const float* x     = (const float*)d_in[0];
    const int*   ei    = (const int*)d_in[1];
    const int*   batch = (const int*)d_in[2];
    const float* W1 = (const float*)d_in[3];
    const float* W2 = (const float*)d_in[5];
    const float* W3 = (const float*)d_in[7];
    const float* g1 = (const float*)d_in[9],  *be1 = (const float*)d_in[10];
    const float* g2 = (const float*)d_in[11], *be2 = (const float*)d_in[12];
    const float* g3 = (const float*)d_in[13], *be3 = (const float*)d_in[14];
    float* out = (float*)d_out;

    const int T = 256;
    dim3 gridH(HID_C / 128, (N_NODES + 127) / 128);
    dim3 gridO(OUT_C / 128, (N_NODES + 127) / 128);

    // CSR / normalization prep
    k_init<<<(N_NODES + T - 1) / T, T>>>();                             // 0
    k_deg_edges<<<(N_EDGES + T - 1) / T, T>>>(ei);                      // 1
    k_dinv<<<(N_NODES + T - 1) / T, T>>>();                             // 2
    k_scan_local<<<SCAN_NB, 256>>>();                                   // 3
    k_scan_bsum<<<1, 256>>>();                                          // 4
    k_scan_final<<<SCAN_NB, 256>>>();                                   // 5
    k_fill<<<(N_EDGES + T - 1) / T, T>>>(ei);                           // 6

    // ---------------- Layer 1: aggregate-first (A(XW) == (AX)W) ----------
    k_aggregate<IN_C, true><<<N_NODES, IN_C>>>(x);          // x -> buf0
    k_split_w<<<(IN_C * HID_C + T - 1) / T, T>>>(W1, IN_C * HID_C);
    k_gemm_tc<false><<<gridH, 512>>>(N_NODES, HID_C, IN_C);
    k_bn_stats<0, HID_C><<<1024, HID_C>>>();
    k_bn_finalize<0, HID_C><<<1, HID_C>>>(g1, be1);

    // ---------------- Layer 2: 256 -> 256 (BN1 fused) ----------------
    k_split_w<<<(HID_C * HID_C + T - 1) / T, T>>>(W2, HID_C * HID_C);
    k_gemm_tc<true><<<gridH, 512>>>(N_NODES, HID_C, HID_C);
    k_aggregate<HID_C, false><<<N_NODES, HID_C>>>(nullptr);
    k_bn_stats<1, HID_C><<<1024, HID_C>>>();
    k_bn_finalize<1, HID_C><<<1, HID_C>>>(g2, be2);

    // ---------------- Layer 3: 256 -> 128 (BN2 fused) ----------------
    k_split_w<<<(HID_C * OUT_C + T - 1) / T, T>>>(W3, HID_C * OUT_C);
    k_gemm_tc<true><<<gridO, 512>>>(N_NODES, OUT_C, HID_C);
    k_aggregate<OUT_C, false><<<N_NODES, OUT_C>>>(nullptr);
    k_bn_stats<2, OUT_C><<<1024, OUT_C>>>();
    k_bn_finalize<2, OUT_C><<<1, OUT_C>>>(g3, be3);

    // ---------------- Global mean pool (BN3 fused) ----------------
    k_pool<<<256, OUT_C>>>(batch);
    k_pool_div<<<(NUM_GRAPHS * OUT_C + T - 1) / T, T>>>(out);
}

// round 17
// speedup vs baseline: 1.0914x; 1.0914x over previous
#include <cuda_runtime.h>
#include <cuda_bf16.h>

// ---------------------------------------------------------------------------
// Problem constants (edge_index / batch_vec are int32 — JAX x64 disabled)
// NOTE: tcgen05 unavailable — harness builds via compute_103 (no 'a').
// ---------------------------------------------------------------------------
#define N_NODES   50000
#define N_EDGES   800000
#define IN_C      128
#define HID_C     256
#define OUT_C     128
#define NUM_GRAPHS 128
#define EPS_BN    1e-5f

// ---------------------------------------------------------------------------
// Scratch (device globals). Ping-pong feature buffers:
//   L1: agg(x)->buf0 ; gemm buf0->buf1
//   L2: gemm(BN1) buf1->buf0 ; agg buf0->buf1
//   L3: gemm(BN2) buf1->buf0 ; agg buf0->buf1 ; pool(BN3) reads buf1
// ---------------------------------------------------------------------------
__device__ float g_buf0[N_NODES * HID_C];
__device__ float g_buf1[N_NODES * HID_C];
// per-layer weight planes: W1 at 0, W2 at 32768, W3 at 98304 (K*N offsets)
#define W1_OFF 0
#define W2_OFF (IN_C * HID_C)
#define W3_OFF (IN_C * HID_C + HID_C * HID_C)
__device__ __nv_bfloat16 g_whi[W3_OFF + HID_C * OUT_C];
__device__ __nv_bfloat16 g_wlo[W3_OFF + HID_C * OUT_C];
__device__ float g_deg [N_NODES];
__device__ float g_dinv[N_NODES];
__device__ int   g_rowptr[N_NODES + 1];
__device__ int   g_cursor[N_NODES];
__device__ int   g_col[N_EDGES];
__device__ float g_val[N_EDGES];
__device__ int   g_lex [N_NODES];
__device__ int   g_boff[256];
__device__ float g_sums  [3 * HID_C];
__device__ float g_sumsqs[3 * HID_C];
__device__ float g_scale[HID_C];
__device__ float g_shift[HID_C];
__device__ float g_cnt  [NUM_GRAPHS];
__device__ float g_pool [NUM_GRAPHS * OUT_C];

// ---------------------------------------------------------------------------
// MMA / ldmatrix wrappers
// ---------------------------------------------------------------------------
__device__ __forceinline__ unsigned smem_u32(const void* p) {
    return (unsigned)__cvta_generic_to_shared(p);
}
__device__ __forceinline__ void ldsm4(unsigned& r0, unsigned& r1,
                                      unsigned& r2, unsigned& r3, unsigned a) {
    asm volatile("ldmatrix.sync.aligned.m8n8.x4.shared.b16 {%0,%1,%2,%3}, [%4];"
                 : "=r"(r0), "=r"(r1), "=r"(r2), "=r"(r3) : "r"(a));
}
__device__ __forceinline__ void ldsm2t(unsigned& r0, unsigned& r1, unsigned a) {
    asm volatile("ldmatrix.sync.aligned.m8n8.x2.trans.shared.b16 {%0,%1}, [%2];"
                 : "=r"(r0), "=r"(r1) : "r"(a));
}
__device__ __forceinline__ void mma16816(float* c, const unsigned* a, const unsigned* b) {
    asm volatile("mma.sync.aligned.m16n8k16.row.col.f32.bf16.bf16.f32 "
                 "{%0,%1,%2,%3}, {%4,%5,%6,%7}, {%8,%9}, {%0,%1,%2,%3};"
                 : "+f"(c[0]), "+f"(c[1]), "+f"(c[2]), "+f"(c[3])
                 : "r"(a[0]), "r"(a[1]), "r"(a[2]), "r"(a[3]), "r"(b[0]), "r"(b[1]));
}

// ---------------------------------------------------------------------------
// Weight hi/lo bf16 split — ALL layers in one launch ([K][N] layouts preserved)
// ---------------------------------------------------------------------------
__global__ void k_split_all(const float* __restrict__ W1,
                            const float* __restrict__ W2,
                            const float* __restrict__ W3) {
    int i = blockIdx.x * blockDim.x + threadIdx.x;
    const int n1 = IN_C * HID_C, n2 = HID_C * HID_C, n3 = HID_C * OUT_C;
    float v; int o;
    if (i < n1)                    { v = W1[i];           o = W1_OFF + i; }
    else if (i < n1 + n2)          { v = W2[i - n1];      o = W2_OFF + (i - n1); }
    else if (i < n1 + n2 + n3)     { v = W3[i - n1 - n2]; o = W3_OFF + (i - n1 - n2); }
    else return;
    __nv_bfloat16 h = __float2bfloat16(v);
    g_whi[o] = h;
    g_wlo[o] = __float2bfloat16(v - __bfloat162float(h));
}

// ---------------------------------------------------------------------------
// Combined init
// ---------------------------------------------------------------------------
__global__ void k_init() {
    int i = blockIdx.x * blockDim.x + threadIdx.x;
    if (i < N_NODES) g_deg[i] = 1.0f;
    if (i < 3 * HID_C) { g_sums[i] = 0.0f; g_sumsqs[i] = 0.0f; }
    if (i < NUM_GRAPHS * OUT_C) g_pool[i] = 0.0f;
    if (i < NUM_GRAPHS) g_cnt[i] = 0.0f;
}

__global__ void k_deg_edges(const int* __restrict__ ei) {
    int e = blockIdx.x * blockDim.x + threadIdx.x;
    if (e < N_EDGES) atomicAdd(&g_deg[ei[N_EDGES + e]], 1.0f);
}

// ---------------------------------------------------------------------------
// Two-level parallel exclusive scan of (deg-1) -> rowptr / cursor.
// dinv computation folded in (reads deg anyway).
// ---------------------------------------------------------------------------
#define SCAN_NB ((N_NODES + 255) / 256)

__global__ void k_scan_local() {
    __shared__ int s[256];
    int t = threadIdx.x, b = blockIdx.x;
    int i = b * 256 + t;
    int v = 0;
    if (i < N_NODES) {
        float d = g_deg[i];
        g_dinv[i] = (d > 0.0f) ? rsqrtf(d) : 0.0f;
        v = (int)d - 1;
    }
    s[t] = v;
    __syncthreads();
    #pragma unroll
    for (int off = 1; off < 256; off <<= 1) {
        int u = (t >= off) ? s[t - off] : 0;
        __syncthreads();
        s[t] += u;
        __syncthreads();
    }
    if (i < N_NODES) g_lex[i] = s[t] - v;
    if (t == 255) g_boff[b] = s[255];
}

__global__ void k_scan_bsum() {
    __shared__ int s[256];
    int t = threadIdx.x;
    int v = (t < SCAN_NB) ? g_boff[t] : 0;
    s[t] = v;
    __syncthreads();
    #pragma unroll
    for (int off = 1; off < 256; off <<= 1) {
        int u = (t >= off) ? s[t - off] : 0;
        __syncthreads();
        s[t] += u;
        __syncthreads();
    }
    if (t < SCAN_NB) g_boff[t] = s[t] - v;
    if (t == 255) g_rowptr[N_NODES] = s[255];
}

__global__ void k_scan_final() {
    int i = blockIdx.x * blockDim.x + threadIdx.x;
    if (i < N_NODES) {
        int r = g_lex[i] + g_boff[i >> 8];
        g_rowptr[i] = r;
        g_cursor[i] = r;
    }
}

__global__ void k_fill(const int* __restrict__ ei) {
    int e = blockIdx.x * blockDim.x + threadIdx.x;
    if (e < N_EDGES) {
        int s = ei[e];
        int d = ei[N_EDGES + e];
        int pos = atomicAdd(&g_cursor[d], 1);
        g_col[pos] = s;
        g_val[pos] = g_dinv[s] * g_dinv[d];
    }
}

// ---------------------------------------------------------------------------
// CSR aggregation
// ---------------------------------------------------------------------------
template <int C, bool EXT>
__global__ void k_aggregate(const float* __restrict__ xin) {
    const float* src = EXT ? xin : (const float*)g_buf0;
    float*       dst = EXT ? (float*)g_buf0 : (float*)g_buf1;
    int i = blockIdx.x;
    int c = threadIdx.x;
    size_t base = (size_t)i * C + c;
    float w = g_dinv[i];
    float acc0 = w * w * src[base];
    float acc1 = 0.f, acc2 = 0.f, acc3 = 0.f;
    int e  = g_rowptr[i];
    int e1 = g_rowptr[i + 1];
    for (; e + 4 <= e1; e += 4) {
        int   s0 = g_col[e],     s1 = g_col[e + 1];
        int   s2 = g_col[e + 2], s3 = g_col[e + 3];
        float v0 = g_val[e],     v1 = g_val[e + 1];
        float v2 = g_val[e + 2], v3 = g_val[e + 3];
        acc0 += v0 * src[(size_t)s0 * C + c];
        acc1 += v1 * src[(size_t)s1 * C + c];
        acc2 += v2 * src[(size_t)s2 * C + c];
        acc3 += v3 * src[(size_t)s3 * C + c];
    }
    for (; e < e1; e++)
        acc0 += g_val[e] * src[(size_t)g_col[e] * C + c];
    dst[base] = (acc0 + acc1) + (acc2 + acc3);
}

// ---------------------------------------------------------------------------
// Tensor-core GEMM (R13 config: 256 thr, 8 warps 2x4, warp tile 64x32,
// block 128x128, BK=32, single-buffered smem) + FRAGMENT double-buffering:
// ks=1 LDSM fragments load while ks=0 MMAs execute (intra-warp ILP — the
// measured limiter; warp count (R16) and smem pipelining (R14) both failed).
// WOFF selects the per-layer weight plane.
// BN=false: g_buf0 -> g_buf1 ; BN=true: relu(BN(g_buf1)) -> g_buf0
// ---------------------------------------------------------------------------
#define GA_STR 40     // A smem row stride (bf16 elems)
#define GB_STR 136    // B smem row stride

struct Frag {
    unsigned ah[4][4], al[4][4];
    unsigned bh[4][2], bl[4][2];
};

template <bool BN>
__device__ __forceinline__ void load_frags(
    Frag& f, const __nv_bfloat16 sa[2][128 * GA_STR],
    const __nv_bfloat16 sb[2][32 * GB_STR],
    int kk, int lane, int wm, int wn) {
    int tsel = lane >> 3, rowin = lane & 7;
    int arow_off = rowin + (tsel & 1) * 8;
    int akcol = kk + (tsel >> 1) * 8;
    #pragma unroll
    for (int mf = 0; mf < 4; mf++) {
        int row = wm * 64 + mf * 16 + arow_off;
        ldsm4(f.ah[mf][0], f.ah[mf][1], f.ah[mf][2], f.ah[mf][3],
              smem_u32(&sa[0][row * GA_STR + akcol]));
        ldsm4(f.al[mf][0], f.al[mf][1], f.al[mf][2], f.al[mf][3],
              smem_u32(&sa[1][row * GA_STR + akcol]));
    }
    int l16 = lane & 15;
    int bkrow = kk + (l16 >> 3) * 8 + (l16 & 7);
    #pragma unroll
    for (int nf = 0; nf < 4; nf++) {
        int n0 = wn * 32 + nf * 8;
        ldsm2t(f.bh[nf][0], f.bh[nf][1], smem_u32(&sb[0][bkrow * GB_STR + n0]));
        ldsm2t(f.bl[nf][0], f.bl[nf][1], smem_u32(&sb[1][bkrow * GB_STR + n0]));
    }
}

template <bool BN>
__global__ __launch_bounds__(256)
void k_gemm_tc(int M, int N, int K, int woff) {
    const float* A = BN ? (const float*)g_buf1 : (const float*)g_buf0;
    float*       D = BN ? (float*)g_buf0 : (float*)g_buf1;
    __shared__ __nv_bfloat16 sa[2][128 * GA_STR];
    __shared__ __nv_bfloat16 sb[2][32 * GB_STR];
    __shared__ float sscale[HID_C], sshift[HID_C];

    int tid = threadIdx.x, lane = tid & 31, warp = tid >> 5;
    int wm = warp >> 2, wn = warp & 3;            // 2 x 4 warp grid
    int bm = blockIdx.y * 128, bn = blockIdx.x * 128;

    const __nv_bfloat16* Whi = g_whi + woff;
    const __nv_bfloat16* Wlo = g_wlo + woff;

    if (BN) {
        for (int i = tid; i < K; i += 256) {
            sscale[i] = g_scale[i];
            sshift[i] = g_shift[i];
        }
    }
    __syncthreads();

    float acc[4][4][4];
    #pragma unroll
    for (int i = 0; i < 4; i++)
        #pragma unroll
        for (int j = 0; j < 4; j++)
            #pragma unroll
            for (int q = 0; q < 4; q++) acc[i][j][q] = 0.0f;

    Frag fr[2];

    for (int k0 = 0; k0 < K; k0 += 32) {
        // --- A: load 128m x 32k fp32, apply BN+ReLU, split hi/lo ---
        #pragma unroll
        for (int r = 0; r < 4; r++) {
            int f = tid + 256 * r;
            int m = f >> 3, kc = f & 7;
            float4 v = make_float4(0.f, 0.f, 0.f, 0.f);
            if (bm + m < M)
                v = *(const float4*)&A[(size_t)(bm + m) * K + k0 + kc * 4];
            if (BN) {
                int kb = k0 + kc * 4;
                v.x = fmaxf(v.x * sscale[kb + 0] + sshift[kb + 0], 0.f);
                v.y = fmaxf(v.y * sscale[kb + 1] + sshift[kb + 1], 0.f);
                v.z = fmaxf(v.z * sscale[kb + 2] + sshift[kb + 2], 0.f);
                v.w = fmaxf(v.w * sscale[kb + 3] + sshift[kb + 3], 0.f);
            }
            __nv_bfloat16 hx = __float2bfloat16(v.x), hy = __float2bfloat16(v.y);
            __nv_bfloat16 hz = __float2bfloat16(v.z), hw = __float2bfloat16(v.w);
            union { __nv_bfloat162 b[2]; uint2 u; } Hi, Lo;
            Hi.b[0] = __nv_bfloat162(hx, hy);
            Hi.b[1] = __nv_bfloat162(hz, hw);
            Lo.b[0] = __nv_bfloat162(__float2bfloat16(v.x - __bfloat162float(hx)),
                                     __float2bfloat16(v.y - __bfloat162float(hy)));
            Lo.b[1] = __nv_bfloat162(__float2bfloat16(v.z - __bfloat162float(hz)),
                                     __float2bfloat16(v.w - __bfloat162float(hw)));
            *(uint2*)&sa[0][m * GA_STR + kc * 4] = Hi.u;
            *(uint2*)&sa[1][m * GA_STR + kc * 4] = Lo.u;
        }
        // --- B: load 32k x 128n (hi+lo planes) ---
        #pragma unroll
        for (int r = 0; r < 2; r++) {
            int f = tid + 256 * r;
            int k = f >> 4, nc = f & 15;
            size_t off = (size_t)(k0 + k) * N + bn + nc * 8;
            *(uint4*)&sb[0][k * GB_STR + nc * 8] = *(const uint4*)&Whi[off];
            *(uint4*)&sb[1][k * GB_STR + nc * 8] = *(const uint4*)&Wlo[off];
        }
        __syncthreads();

        // frag pipeline: load ks=0; then per ks, prefetch ks+1 before MMAs
        load_frags<BN>(fr[0], sa, sb, 0, lane, wm, wn);
        #pragma unroll
        for (int ks = 0; ks < 2; ks++) {
            if (ks == 0)
                load_frags<BN>(fr[1], sa, sb, 16, lane, wm, wn);
            Frag& f = fr[ks];
            #pragma unroll
            for (int mf = 0; mf < 4; mf++)
                #pragma unroll
                for (int nf = 0; nf < 4; nf++)
                    mma16816(acc[mf][nf], f.ah[mf], f.bh[nf]);
            #pragma unroll
            for (int mf = 0; mf < 4; mf++)
                #pragma unroll
                for (int nf = 0; nf < 4; nf++)
                    mma16816(acc[mf][nf], f.ah[mf], f.bl[nf]);
            #pragma unroll
            for (int mf = 0; mf < 4; mf++)
                #pragma unroll
                for (int nf = 0; nf < 4; nf++)
                    mma16816(acc[mf][nf], f.al[mf], f.bh[nf]);
        }
        __syncthreads();
    }

    int grp = lane >> 2, tg = lane & 3;
    #pragma unroll
    for (int mf = 0; mf < 4; mf++) {
        #pragma unroll
        for (int nf = 0; nf < 4; nf++) {
            int row = bm + wm * 64 + mf * 16 + grp;
            int col = bn + wn * 32 + nf * 8 + tg * 2;
            if (row < M)
                *(float2*)&D[(size_t)row * N + col] =
                    make_float2(acc[mf][nf][0], acc[mf][nf][1]);
            if (row + 8 < M)
                *(float2*)&D[(size_t)(row + 8) * N + col] =
                    make_float2(acc[mf][nf][2], acc[mf][nf][3]);
        }
    }
}

// ---------------------------------------------------------------------------
// BN statistics + finalize
// ---------------------------------------------------------------------------
template <int L, int C>
__global__ void k_bn_stats() {
    int c = threadIdx.x;
    float s = 0.0f, s2 = 0.0f;
    for (int i = blockIdx.x; i < N_NODES; i += gridDim.x) {
        float v = g_buf1[(size_t)i * C + c];
        s += v; s2 += v * v;
    }
    atomicAdd(&g_sums[L * HID_C + c], s);
    atomicAdd(&g_sumsqs[L * HID_C + c], s2);
}

template <int L, int C>
__global__ void k_bn_finalize(const float* __restrict__ gamma,
                              const float* __restrict__ beta) {
    int c = threadIdx.x;
    if (c < C) {
        float mu  = g_sums[L * HID_C + c] * (1.0f / N_NODES);
        float var = g_sumsqs[L * HID_C + c] * (1.0f / N_NODES) - mu * mu;
        float inv = rsqrtf(var + EPS_BN);
        float sc  = gamma[c] * inv;
        g_scale[c] = sc;
        g_shift[c] = beta[c] - mu * sc;
    }
}

// ---------------------------------------------------------------------------
// Global mean pool with layer-3 BN+ReLU fused on the read
// ---------------------------------------------------------------------------
__global__ void k_pool(const int* __restrict__ batch) {
    int c = threadIdx.x;
    int per = (N_NODES + gridDim.x - 1) / gridDim.x;
    int i0 = blockIdx.x * per;
    int i1 = min(i0 + per, N_NODES);
    if (i0 >= i1) return;

    float sc = g_scale[c], sh = g_shift[c];
    int curg = batch[i0];
    float acc = 0.0f, n = 0.0f;
    for (int i = i0; i < i1; i++) {
        int g = batch[i];
        if (g != curg) {
            atomicAdd(&g_pool[curg * OUT_C + c], acc);
            if (c == 0) atomicAdd(&g_cnt[curg], n);
            acc = 0.0f; n = 0.0f; curg = g;
        }
        acc += fmaxf(g_buf1[(size_t)i * OUT_C + c] * sc + sh, 0.0f);
        n += 1.0f;
    }
    atomicAdd(&g_pool[curg * OUT_C + c], acc);
    if (c == 0) atomicAdd(&g_cnt[curg], n);
}

__global__ void k_pool_div(float* __restrict__ out) {
    int i = blockIdx.x * blockDim.x + threadIdx.x;
    if (i < NUM_GRAPHS * OUT_C) {
        float cnt = g_cnt[i / OUT_C];
        out[i] = g_pool[i] / fmaxf(cnt, 1.0f);
    }
}

// ---------------------------------------------------------------------------
// Host orchestration (kernel launches ONLY — graph-capture safe)
// ---------------------------------------------------------------------------
extern "C" void kernel_launch(void* const* d_in, const int* in_sizes, int n_in,
                              void* d_out, int out_size) {
    const float* x     = (const float*)d_in[0];
    const int*   ei    = (const int*)d_in[1];
    const int*   batch = (const int*)d_in[2];
    const float* W1 = (const float*)d_in[3];
    const float* W2 = (const float*)d_in[5];
    const float* W3 = (const float*)d_in[7];
    const float* g1 = (const float*)d_in[9],  *be1 = (const float*)d_in[10];
    const float* g2 = (const float*)d_in[11], *be2 = (const float*)d_in[12];
    const float* g3 = (const float*)d_in[13], *be3 = (const float*)d_in[14];
    float* out = (float*)d_out;

    const int T = 256;
    const int W_TOTAL = IN_C * HID_C + HID_C * HID_C + HID_C * OUT_C;
    dim3 gridH(HID_C / 128, (N_NODES + 127) / 128);
    dim3 gridO(OUT_C / 128, (N_NODES + 127) / 128);

    // CSR / normalization prep + all weight splits upfront
    k_init<<<(N_NODES + T - 1) / T, T>>>();                             // 0
    k_split_all<<<(W_TOTAL + T - 1) / T, T>>>(W1, W2, W3);              // 1
    k_deg_edges<<<(N_EDGES + T - 1) / T, T>>>(ei);                      // 2
    k_scan_local<<<SCAN_NB, 256>>>();                                   // 3 (dinv fused)
    k_scan_bsum<<<1, 256>>>();                                          // 4
    k_scan_final<<<SCAN_NB, 256>>>();                                   // 5
    k_fill<<<(N_EDGES + T - 1) / T, T>>>(ei);                           // 6

    // ---------------- Layer 1: aggregate-first (A(XW) == (AX)W) ----------
    k_aggregate<IN_C, true><<<N_NODES, IN_C>>>(x);          // x -> buf0
    k_gemm_tc<false><<<gridH, 256>>>(N_NODES, HID_C, IN_C, W1_OFF);
    k_bn_stats<0, HID_C><<<1024, HID_C>>>();
    k_bn_finalize<0, HID_C><<<1, HID_C>>>(g1, be1);

    // ---------------- Layer 2: 256 -> 256 (BN1 fused) ----------------
    k_gemm_tc<true><<<gridH, 256>>>(N_NODES, HID_C, HID_C, W2_OFF);
    k_aggregate<HID_C, false><<<N_NODES, HID_C>>>(nullptr);
    k_bn_stats<1, HID_C><<<1024, HID_C>>>();
    k_bn_finalize<1, HID_C><<<1, HID_C>>>(g2, be2);

    // ---------------- Layer 3: 256 -> 128 (BN2 fused) ----------------
    k_gemm_tc<true><<<gridO, 256>>>(N_NODES, OUT_C, HID_C, W3_OFF);
    k_aggregate<OUT_C, false><<<N_NODES, OUT_C>>>(nullptr);
    k_bn_stats<2, OUT_C><<<1024, OUT_C>>>();
    k_bn_finalize<2, OUT_C><<<1, OUT_C>>>(g3, be3);

    // ---------------- Global mean pool (BN3 fused) ----------------
    k_pool<<<256, OUT_C>>>(batch);
    k_pool_div<<<(NUM_GRAPHS * OUT_C + T - 1) / T, T>>>(out);
}